// round 3
// baseline (speedup 1.0000x reference)
#include <cuda_runtime.h>
#include <math.h>

// Problem constants (fixed by the dataset)
#define T_TOK 2048
#define DIM   2048
#define NE    8
#define NI    2048
#define NTOPK 2
#define CAP   2048          // worst-case tokens per expert
#define SOFTCAP 30.0f

// ---------------- device scratch (no runtime allocation) ----------------
__device__ float g_h[(size_t)NE * CAP * NI];    // GLU hidden, padded per-expert slots (134 MB)
__device__ float g_y[(size_t)NE * CAP * DIM];   // per-selection expert output, scaled (134 MB)
__device__ int   g_sel_token[NE * CAP];
__device__ float g_sel_w[NE * CAP];
__device__ int   g_slot_of[T_TOK * NTOPK];
__device__ int   g_count[NE];
__device__ int   g_topk_idx[T_TOK * NTOPK];
__device__ float g_topk_w[T_TOK * NTOPK];

__device__ __forceinline__ float gelu_exact(float v) {
    return 0.5f * v * (1.0f + erff(v * 0.70710678118654752440f));
}

// ---------------- 1) Router: logits -> softcap -> softmax -> top-2 ----------------
__global__ void router_kernel(const float* __restrict__ x,
                              const float* __restrict__ wg) {
    const int t   = blockIdx.x;
    const int tid = threadIdx.x;      // 256 threads
    const float* xr = x + (size_t)t * DIM;

    float acc[NE];
#pragma unroll
    for (int e = 0; e < NE; e++) acc[e] = 0.f;
    for (int d = tid; d < DIM; d += 256) {
        float xv = xr[d];
#pragma unroll
        for (int e = 0; e < NE; e++) acc[e] += xv * wg[e * DIM + d];
    }

    __shared__ float sh[NE][256];
#pragma unroll
    for (int e = 0; e < NE; e++) sh[e][tid] = acc[e];
    __syncthreads();
    for (int s = 128; s > 0; s >>= 1) {
        if (tid < s) {
#pragma unroll
            for (int e = 0; e < NE; e++) sh[e][tid] += sh[e][tid + s];
        }
        __syncthreads();
    }

    if (tid == 0) {
        float l[NE];
        float mx = -1e30f;
#pragma unroll
        for (int e = 0; e < NE; e++) {
            l[e] = SOFTCAP * tanhf(sh[e][0] / SOFTCAP);
            mx = fmaxf(mx, l[e]);
        }
        float sum = 0.f;
#pragma unroll
        for (int e = 0; e < NE; e++) { l[e] = expf(l[e] - mx); sum += l[e]; }
        float inv = 1.f / sum;
        // top-2 (ties -> lower index first, matching jax.lax.top_k)
        int i0 = 0;
#pragma unroll
        for (int e = 1; e < NE; e++) if (l[e] > l[i0]) i0 = e;
        int i1 = (i0 == 0) ? 1 : 0;
#pragma unroll
        for (int e = 0; e < NE; e++) {
            if (e == i0) continue;
            if (l[e] > l[i1]) i1 = e;
        }
        g_topk_idx[t * 2 + 0] = i0; g_topk_w[t * 2 + 0] = l[i0] * inv;
        g_topk_idx[t * 2 + 1] = i1; g_topk_w[t * 2 + 1] = l[i1] * inv;
    }
}

// ---------------- 2) Deterministic counting sort by expert (1 block, warp/expert) ----------------
__global__ void sort_kernel() {
    const int wid  = threadIdx.x >> 5;   // expert id (8 warps)
    const int lane = threadIdx.x & 31;
    if (wid >= NE) return;
    int running = 0;
    for (int base = 0; base < T_TOK * NTOPK; base += 32) {
        const int s  = base + lane;
        const int ex = g_topk_idx[s];
        const bool p = (ex == wid);
        const unsigned m = __ballot_sync(0xffffffffu, p);
        if (p) {
            const int rank = running + __popc(m & ((1u << lane) - 1u));
            const int pos  = wid * CAP + rank;
            g_sel_token[pos] = s >> 1;
            g_sel_w[pos]     = g_topk_w[s];
            g_slot_of[s]     = pos;
        }
        running += __popc(m);
    }
    if (lane == 0) g_count[wid] = running;
}

// ---------------- 3) Grouped GEMM1: h = gelu(Xsel @ W1^T) * (Xsel @ W3^T) ----------------
// Tile: 128 rows (selections) x 64 cols (I), K-tile 16. 256 threads, 8x4 per thread, dual-B.
__global__ __launch_bounds__(256) void gemm1_kernel(const float* __restrict__ x,
                                                    const float* __restrict__ w1,
                                                    const float* __restrict__ w3) {
    const int e    = blockIdx.y >> 4;     // 16 m-tiles per expert (CAP/128)
    const int mt   = blockIdx.y & 15;
    const int row0 = mt * 128;
    const int cnt  = g_count[e];
    if (row0 >= cnt) return;
    const int n0 = blockIdx.x * 64;

    __shared__ float As[16][128];
    __shared__ float B1s[16][64];
    __shared__ float B3s[16][64];
    __shared__ int   tok[128];

    const int tid = threadIdx.x;
    if (tid < 128) {
        const int r = row0 + tid;
        tok[tid] = (r < cnt) ? g_sel_token[e * CAP + r] : 0;
    }
    __syncthreads();

    const int tx = tid & 15, ty = tid >> 4;
    float acc1[8][4], acc3[8][4];
#pragma unroll
    for (int i = 0; i < 8; i++)
#pragma unroll
        for (int j = 0; j < 4; j++) { acc1[i][j] = 0.f; acc3[i][j] = 0.f; }

    // loader mappings
    const int am = tid >> 1;              // 0..127
    const int ak = (tid & 1) * 8;         // 0 or 8
    const int bn = tid >> 2;              // 0..63
    const int bk = (tid & 3) * 4;         // 0,4,8,12
    const float* xp  = x  + (size_t)tok[am] * DIM + ak;
    const float* w1p = w1 + ((size_t)(e * NI + n0 + bn)) * DIM + bk;
    const float* w3p = w3 + ((size_t)(e * NI + n0 + bn)) * DIM + bk;

    for (int kb = 0; kb < DIM; kb += 16) {
        float4 a0 = *(const float4*)(xp + kb);
        float4 a1 = *(const float4*)(xp + kb + 4);
        As[ak + 0][am] = a0.x; As[ak + 1][am] = a0.y; As[ak + 2][am] = a0.z; As[ak + 3][am] = a0.w;
        As[ak + 4][am] = a1.x; As[ak + 5][am] = a1.y; As[ak + 6][am] = a1.z; As[ak + 7][am] = a1.w;
        float4 b1 = *(const float4*)(w1p + kb);
        B1s[bk + 0][bn] = b1.x; B1s[bk + 1][bn] = b1.y; B1s[bk + 2][bn] = b1.z; B1s[bk + 3][bn] = b1.w;
        float4 b3 = *(const float4*)(w3p + kb);
        B3s[bk + 0][bn] = b3.x; B3s[bk + 1][bn] = b3.y; B3s[bk + 2][bn] = b3.z; B3s[bk + 3][bn] = b3.w;
        __syncthreads();
#pragma unroll
        for (int k = 0; k < 16; k++) {
            float4 av0 = *(const float4*)&As[k][ty * 8];
            float4 av1 = *(const float4*)&As[k][ty * 8 + 4];
            float4 bv1 = *(const float4*)&B1s[k][tx * 4];
            float4 bv3 = *(const float4*)&B3s[k][tx * 4];
            float a[8] = {av0.x, av0.y, av0.z, av0.w, av1.x, av1.y, av1.z, av1.w};
            float c1[4] = {bv1.x, bv1.y, bv1.z, bv1.w};
            float c3[4] = {bv3.x, bv3.y, bv3.z, bv3.w};
#pragma unroll
            for (int i = 0; i < 8; i++) {
#pragma unroll
                for (int j = 0; j < 4; j++) {
                    acc1[i][j] += a[i] * c1[j];
                    acc3[i][j] += a[i] * c3[j];
                }
            }
        }
        __syncthreads();
    }

    // epilogue: h = gelu(a) * b
#pragma unroll
    for (int i = 0; i < 8; i++) {
        const int r = row0 + ty * 8 + i;
        if (r < cnt) {
            float4 o;
            o.x = gelu_exact(acc1[i][0]) * acc3[i][0];
            o.y = gelu_exact(acc1[i][1]) * acc3[i][1];
            o.z = gelu_exact(acc1[i][2]) * acc3[i][2];
            o.w = gelu_exact(acc1[i][3]) * acc3[i][3];
            *(float4*)(g_h + ((size_t)(e * CAP + r)) * NI + n0 + tx * 4) = o;
        }
    }
}

// ---------------- 4) Grouped GEMM2: y = weight * (h @ W2^T) ----------------
// Tile: 128 rows x 128 cols (D), K-tile 16. 256 threads, 8x8 per thread.
__global__ __launch_bounds__(256) void gemm2_kernel(const float* __restrict__ w2) {
    const int e    = blockIdx.y >> 4;
    const int mt   = blockIdx.y & 15;
    const int row0 = mt * 128;
    const int cnt  = g_count[e];
    if (row0 >= cnt) return;
    const int n0 = blockIdx.x * 128;

    __shared__ float As[16][128];
    __shared__ float Bs[16][128];

    const int tid = threadIdx.x;
    const int tx = tid & 15, ty = tid >> 4;
    float acc[8][8];
#pragma unroll
    for (int i = 0; i < 8; i++)
#pragma unroll
        for (int j = 0; j < 8; j++) acc[i][j] = 0.f;

    const int am = tid >> 1;
    const int ak = (tid & 1) * 8;
    const float* ap = g_h + ((size_t)(e * CAP + row0 + am)) * NI + ak;
    const float* bp = w2  + ((size_t)(e * DIM + n0 + am)) * NI + ak;

    for (int kb = 0; kb < NI; kb += 16) {
        float4 a0 = *(const float4*)(ap + kb);
        float4 a1 = *(const float4*)(ap + kb + 4);
        As[ak + 0][am] = a0.x; As[ak + 1][am] = a0.y; As[ak + 2][am] = a0.z; As[ak + 3][am] = a0.w;
        As[ak + 4][am] = a1.x; As[ak + 5][am] = a1.y; As[ak + 6][am] = a1.z; As[ak + 7][am] = a1.w;
        float4 b0 = *(const float4*)(bp + kb);
        float4 b1 = *(const float4*)(bp + kb + 4);
        Bs[ak + 0][am] = b0.x; Bs[ak + 1][am] = b0.y; Bs[ak + 2][am] = b0.z; Bs[ak + 3][am] = b0.w;
        Bs[ak + 4][am] = b1.x; Bs[ak + 5][am] = b1.y; Bs[ak + 6][am] = b1.z; Bs[ak + 7][am] = b1.w;
        __syncthreads();
#pragma unroll
        for (int k = 0; k < 16; k++) {
            float4 av0 = *(const float4*)&As[k][ty * 8];
            float4 av1 = *(const float4*)&As[k][ty * 8 + 4];
            float4 bv0 = *(const float4*)&Bs[k][tx * 8];
            float4 bv1 = *(const float4*)&Bs[k][tx * 8 + 4];
            float a[8] = {av0.x, av0.y, av0.z, av0.w, av1.x, av1.y, av1.z, av1.w};
            float b[8] = {bv0.x, bv0.y, bv0.z, bv0.w, bv1.x, bv1.y, bv1.z, bv1.w};
#pragma unroll
            for (int i = 0; i < 8; i++)
#pragma unroll
                for (int j = 0; j < 8; j++) acc[i][j] += a[i] * b[j];
        }
        __syncthreads();
    }

    // epilogue: scale by routing weight, store to per-selection y buffer
#pragma unroll
    for (int i = 0; i < 8; i++) {
        const int r = row0 + ty * 8 + i;
        if (r < cnt) {
            const float w = g_sel_w[e * CAP + r];
            float* yp = g_y + ((size_t)(e * CAP + r)) * DIM + n0 + tx * 8;
            float4 o0, o1;
            o0.x = acc[i][0] * w; o0.y = acc[i][1] * w; o0.z = acc[i][2] * w; o0.w = acc[i][3] * w;
            o1.x = acc[i][4] * w; o1.y = acc[i][5] * w; o1.z = acc[i][6] * w; o1.w = acc[i][7] * w;
            *(float4*)yp = o0;
            *(float4*)(yp + 4) = o1;
        }
    }
}

// ---------------- 5) Combine: out[t] = y[slot(t,0)] + y[slot(t,1)] ----------------
__global__ void combine_kernel(float* __restrict__ out) {
    const int t = blockIdx.x;
    const int d = blockIdx.y * 256 + threadIdx.x;
    const int s0 = g_slot_of[t * 2 + 0];
    const int s1 = g_slot_of[t * 2 + 1];
    out[(size_t)t * DIM + d] = g_y[(size_t)s0 * DIM + d] + g_y[(size_t)s1 * DIM + d];
}

// ---------------- launch ----------------
extern "C" void kernel_launch(void* const* d_in, const int* in_sizes, int n_in,
                              void* d_out, int out_size) {
    const float* x      = (const float*)d_in[0];
    const float* w_gate = (const float*)d_in[1];
    const float* w1     = (const float*)d_in[2];
    const float* w3     = (const float*)d_in[3];
    const float* w2     = (const float*)d_in[4];
    float* out = (float*)d_out;
    (void)in_sizes; (void)n_in; (void)out_size;

    router_kernel<<<T_TOK, 256>>>(x, w_gate);
    sort_kernel<<<1, 256>>>();
    gemm1_kernel<<<dim3(NI / 64, NE * (CAP / 128)), 256>>>(x, w1, w3);
    gemm2_kernel<<<dim3(DIM / 128, NE * (CAP / 128)), 256>>>(w2);
    combine_kernel<<<dim3(T_TOK, DIM / 256), 256>>>(out);
}

// round 5
// speedup vs baseline: 4.0186x; 4.0186x over previous
#include <cuda_runtime.h>
#include <cuda_fp16.h>
#include <math.h>
#include <stdint.h>

// Problem constants (fixed by the dataset)
#define T_TOK 2048
#define DIM   2048
#define NE    8
#define NI    2048
#define CAP   2048
#define SOFTCAP 30.0f

// ---------------- device scratch (no runtime allocation) ----------------
__device__ __half g_xh [(size_t)T_TOK * DIM];
__device__ __half g_w1h[(size_t)NE * NI * DIM];
__device__ __half g_w3h[(size_t)NE * NI * DIM];
__device__ __half g_w2h[(size_t)NE * DIM * NI];
__device__ __half g_hh [(size_t)NE * CAP * NI];     // GLU hidden, fp16
__device__ float  g_y  [(size_t)NE * CAP * DIM];    // per-selection scaled out
__device__ int    g_sel_token[NE * CAP];
__device__ float  g_sel_w[NE * CAP];
__device__ int    g_slot_of[T_TOK * 2];
__device__ int    g_count[NE];
__device__ int    g_topk_idx[T_TOK * 2];
__device__ float  g_topk_w[T_TOK * 2];

// ---------------- helpers ----------------
__device__ __forceinline__ float gelu_exact(float v) {
    return 0.5f * v * (1.0f + erff(v * 0.70710678118654752440f));
}
__device__ __forceinline__ uint32_t smem_u32(const void* p) {
    uint32_t a;
    asm("{ .reg .u64 t; cvta.to.shared.u64 t, %1; cvt.u32.u64 %0, t; }" : "=r"(a) : "l"(p));
    return a;
}
__device__ __forceinline__ void cp16(uint32_t dst, const void* src) {
    asm volatile("cp.async.cg.shared.global [%0], [%1], 16;" :: "r"(dst), "l"(src) : "memory");
}
#define CP_COMMIT() asm volatile("cp.async.commit_group;" ::: "memory")

#define LDSM4(r0, r1, r2, r3, addr) \
    asm volatile("ldmatrix.sync.aligned.m8n8.x4.shared.b16 {%0,%1,%2,%3}, [%4];" \
                 : "=r"(r0), "=r"(r1), "=r"(r2), "=r"(r3) : "r"(addr))

#define MMA4(c, a, b0, b1) \
    asm volatile("mma.sync.aligned.m16n8k16.row.col.f32.f16.f16.f32 " \
                 "{%0,%1,%2,%3}, {%4,%5,%6,%7}, {%8,%9}, {%0,%1,%2,%3};" \
                 : "+f"((c)[0]), "+f"((c)[1]), "+f"((c)[2]), "+f"((c)[3]) \
                 : "r"((a)[0]), "r"((a)[1]), "r"((a)[2]), "r"((a)[3]), \
                   "r"(b0), "r"(b1))

// smem tile geometry: rows of 32 halves (64B) + 16B pad -> 80B row stride.
// cp.async writes and ldmatrix reads are both bank-conflict-free (stride 20
// words; 8-row phase pattern r*20 mod 32 = {0,20,8,28,16,4,24,12}).
#define ROWB 80

// ---------------- 1) Router (fp32, exact) ----------------
__global__ void router_kernel(const float* __restrict__ x,
                              const float* __restrict__ wg) {
    const int t   = blockIdx.x;
    const int tid = threadIdx.x;
    const float* xr = x + (size_t)t * DIM;

    float acc[NE];
#pragma unroll
    for (int e = 0; e < NE; e++) acc[e] = 0.f;
    for (int d = tid; d < DIM; d += 256) {
        float xv = xr[d];
#pragma unroll
        for (int e = 0; e < NE; e++) acc[e] += xv * wg[e * DIM + d];
    }

    __shared__ float sh[NE][256];
#pragma unroll
    for (int e = 0; e < NE; e++) sh[e][tid] = acc[e];
    __syncthreads();
    for (int s = 128; s > 0; s >>= 1) {
        if (tid < s) {
#pragma unroll
            for (int e = 0; e < NE; e++) sh[e][tid] += sh[e][tid + s];
        }
        __syncthreads();
    }

    if (tid == 0) {
        float l[NE];
        float mx = -1e30f;
#pragma unroll
        for (int e = 0; e < NE; e++) {
            l[e] = SOFTCAP * tanhf(sh[e][0] / SOFTCAP);
            mx = fmaxf(mx, l[e]);
        }
        float sum = 0.f;
#pragma unroll
        for (int e = 0; e < NE; e++) { l[e] = expf(l[e] - mx); sum += l[e]; }
        float inv = 1.f / sum;
        int i0 = 0;
#pragma unroll
        for (int e = 1; e < NE; e++) if (l[e] > l[i0]) i0 = e;
        int i1 = (i0 == 0) ? 1 : 0;
#pragma unroll
        for (int e = 0; e < NE; e++) {
            if (e == i0) continue;
            if (l[e] > l[i1]) i1 = e;
        }
        g_topk_idx[t * 2 + 0] = i0; g_topk_w[t * 2 + 0] = l[i0] * inv;
        g_topk_idx[t * 2 + 1] = i1; g_topk_w[t * 2 + 1] = l[i1] * inv;
    }
}

// ---------------- 2) Deterministic counting sort by expert ----------------
__global__ void sort_kernel() {
    const int wid  = threadIdx.x >> 5;
    const int lane = threadIdx.x & 31;
    if (wid >= NE) return;
    int running = 0;
    for (int base = 0; base < T_TOK * 2; base += 32) {
        const int s  = base + lane;
        const int ex = g_topk_idx[s];
        const bool p = (ex == wid);
        const unsigned m = __ballot_sync(0xffffffffu, p);
        if (p) {
            const int rank = running + __popc(m & ((1u << lane) - 1u));
            const int pos  = wid * CAP + rank;
            g_sel_token[pos] = s >> 1;
            g_sel_w[pos]     = g_topk_w[s];
            g_slot_of[s]     = pos;
        }
        running += __popc(m);
    }
    if (lane == 0) g_count[wid] = running;
}

// ---------------- 3) fp32 -> fp16 convert ----------------
__global__ void cvt_half_kernel(const float* __restrict__ src,
                                __half* __restrict__ dst, long n4) {
    long i = (long)blockIdx.x * 256 + threadIdx.x;
    const long stride = (long)gridDim.x * 256;
    for (; i < n4; i += stride) {
        float4 v = ((const float4*)src)[i];
        __half2 h0 = __floats2half2_rn(v.x, v.y);
        __half2 h1 = __floats2half2_rn(v.z, v.w);
        uint2 o;
        o.x = *(uint32_t*)&h0;
        o.y = *(uint32_t*)&h1;
        ((uint2*)dst)[i] = o;
    }
}

// ---------------- 4) GEMM1: h = gelu(Xsel W1^T) * (Xsel W3^T) ----------------
// CTA 128(M) x 64(N), dual B. k-tile 32, 4-stage cp.async.
// 8 warps: wm = wid&1 (m 64), wn = wid>>1 (n 16).
#define STG1 20480   // A 128*80 + B1 64*80 + B3 64*80

__global__ __launch_bounds__(256) void mma1_kernel() {
    const int e    = blockIdx.y >> 4;
    const int mt   = blockIdx.y & 15;
    const int row0 = mt * 128;
    const int cnt  = g_count[e];
    if (row0 >= cnt) return;
    const int n0 = blockIdx.x * 64;

    extern __shared__ char dsm[];
    __shared__ int tok[128];

    const int tid  = threadIdx.x;
    const int wid  = tid >> 5;
    const int lane = tid & 31;

    if (tid < 128) {
        const int r = row0 + tid;
        tok[tid] = (r < cnt) ? g_sel_token[e * CAP + r] : 0;
    }
    __syncthreads();

    const uint32_t dyn0 = smem_u32(dsm);

    const int seg = tid & 3;        // k segment (8 halves)
    const int r64 = tid >> 2;       // 0..63
    const __half* a0src = g_xh  + (size_t)tok[r64]      * DIM + seg * 8;
    const __half* a1src = g_xh  + (size_t)tok[r64 + 64] * DIM + seg * 8;
    const __half* b1src = g_w1h + ((size_t)e * NI + n0 + r64) * DIM + seg * 8;
    const __half* b3src = g_w3h + ((size_t)e * NI + n0 + r64) * DIM + seg * 8;
    const uint32_t dA0 = (uint32_t)(r64 * ROWB + seg * 16);
    const uint32_t dA1 = (uint32_t)((r64 + 64) * ROWB + seg * 16);

    auto load_stage = [&](int s, int kb) {
        const uint32_t b = dyn0 + s * STG1;
        cp16(b + dA0, a0src + kb);
        cp16(b + dA1, a1src + kb);
        cp16(b + 10240 + dA0, b1src + kb);
        cp16(b + 15360 + dA0, b3src + kb);
        CP_COMMIT();
    };
    load_stage(0, 0); load_stage(1, 32); load_stage(2, 64);

    const int wm = wid & 1, wn = wid >> 1;
    float c1[4][2][4], c3[4][2][4];
#pragma unroll
    for (int mf = 0; mf < 4; mf++)
#pragma unroll
        for (int nf = 0; nf < 2; nf++)
#pragma unroll
            for (int k = 0; k < 4; k++) { c1[mf][nf][k] = 0.f; c3[mf][nf][k] = 0.f; }

    const uint32_t lrow = (uint32_t)((lane & 15) * ROWB + (lane >> 4) * 16);

    for (int i = 0; i < 64; i++) {
        const int s = i & 3;
        asm volatile("cp.async.wait_group 2;" ::: "memory");
        __syncthreads();
        const int nx = i + 3;
        if (nx < 64) load_stage(nx & 3, nx * 32); else CP_COMMIT();

        const uint32_t sb  = dyn0 + s * STG1;
        const uint32_t Ab  = sb + (uint32_t)(wm * 64 * ROWB) + lrow;
        const uint32_t B1b = sb + 10240 + (uint32_t)(wn * 16 * ROWB) + lrow;
        const uint32_t B3b = sb + 15360 + (uint32_t)(wn * 16 * ROWB) + lrow;
#pragma unroll
        for (int kk = 0; kk < 2; kk++) {
            uint32_t p1[4], p3[4];
            LDSM4(p1[0], p1[1], p1[2], p1[3], B1b + kk * 32);
            LDSM4(p3[0], p3[1], p3[2], p3[3], B3b + kk * 32);
#pragma unroll
            for (int mf = 0; mf < 4; mf++) {
                uint32_t a[4];
                LDSM4(a[0], a[1], a[2], a[3], Ab + mf * (16 * ROWB) + kk * 32);
                MMA4(c1[mf][0], a, p1[0], p1[2]);
                MMA4(c1[mf][1], a, p1[1], p1[3]);
                MMA4(c3[mf][0], a, p3[0], p3[2]);
                MMA4(c3[mf][1], a, p3[1], p3[3]);
            }
        }
    }

    // epilogue: h = gelu(a) * b -> fp16
#pragma unroll
    for (int mf = 0; mf < 4; mf++) {
        const int rb = row0 + wm * 64 + mf * 16 + (lane >> 2);
#pragma unroll
        for (int nf = 0; nf < 2; nf++) {
            const int col = n0 + wn * 16 + nf * 8 + (lane & 3) * 2;
            if (rb < cnt) {
                __half2 h = __floats2half2_rn(
                    gelu_exact(c1[mf][nf][0]) * c3[mf][nf][0],
                    gelu_exact(c1[mf][nf][1]) * c3[mf][nf][1]);
                *(__half2*)(g_hh + ((size_t)(e * CAP) + rb) * NI + col) = h;
            }
            if (rb + 8 < cnt) {
                __half2 h = __floats2half2_rn(
                    gelu_exact(c1[mf][nf][2]) * c3[mf][nf][2],
                    gelu_exact(c1[mf][nf][3]) * c3[mf][nf][3]);
                *(__half2*)(g_hh + ((size_t)(e * CAP) + rb + 8) * NI + col) = h;
            }
        }
    }
}

// ---------------- 5) GEMM2: y = sel_w * (h W2^T) ----------------
// CTA 128(M) x 128(N). k-tile 32, 4-stage. warps: wm = wid&1, wn = wid>>1 (n 32).
#define STG2 20480   // A 128*80 + B 128*80

__global__ __launch_bounds__(256) void mma2_kernel() {
    const int e    = blockIdx.y >> 4;
    const int mt   = blockIdx.y & 15;
    const int row0 = mt * 128;
    const int cnt  = g_count[e];
    if (row0 >= cnt) return;
    const int n0 = blockIdx.x * 128;

    extern __shared__ char dsm[];

    const int tid  = threadIdx.x;
    const int wid  = tid >> 5;
    const int lane = tid & 31;

    const uint32_t dyn0 = smem_u32(dsm);

    const int seg = tid & 3;
    const int r64 = tid >> 2;
    const __half* a0src = g_hh  + ((size_t)(e * CAP) + row0 + r64)      * NI + seg * 8;
    const __half* a1src = g_hh  + ((size_t)(e * CAP) + row0 + r64 + 64) * NI + seg * 8;
    const __half* b0src = g_w2h + ((size_t)e * DIM + n0 + r64)      * NI + seg * 8;
    const __half* b1src = g_w2h + ((size_t)e * DIM + n0 + r64 + 64) * NI + seg * 8;
    const uint32_t d0 = (uint32_t)(r64 * ROWB + seg * 16);
    const uint32_t d1 = (uint32_t)((r64 + 64) * ROWB + seg * 16);

    auto load_stage = [&](int s, int kb) {
        const uint32_t b = dyn0 + s * STG2;
        cp16(b + d0, a0src + kb);
        cp16(b + d1, a1src + kb);
        cp16(b + 10240 + d0, b0src + kb);
        cp16(b + 10240 + d1, b1src + kb);
        CP_COMMIT();
    };
    load_stage(0, 0); load_stage(1, 32); load_stage(2, 64);

    const int wm = wid & 1, wn = wid >> 1;
    float c[4][4][4];
#pragma unroll
    for (int mf = 0; mf < 4; mf++)
#pragma unroll
        for (int nf = 0; nf < 4; nf++)
#pragma unroll
            for (int k = 0; k < 4; k++) c[mf][nf][k] = 0.f;

    const uint32_t lrow = (uint32_t)((lane & 15) * ROWB + (lane >> 4) * 16);

    for (int i = 0; i < 64; i++) {
        const int s = i & 3;
        asm volatile("cp.async.wait_group 2;" ::: "memory");
        __syncthreads();
        const int nx = i + 3;
        if (nx < 64) load_stage(nx & 3, nx * 32); else CP_COMMIT();

        const uint32_t sb = dyn0 + s * STG2;
        const uint32_t Ab = sb + (uint32_t)(wm * 64 * ROWB) + lrow;
        const uint32_t Bb = sb + 10240 + (uint32_t)(wn * 32 * ROWB) + lrow;
#pragma unroll
        for (int kk = 0; kk < 2; kk++) {
            uint32_t bb0[4], bb1v[4];
            LDSM4(bb0[0], bb0[1], bb0[2], bb0[3], Bb + kk * 32);
            LDSM4(bb1v[0], bb1v[1], bb1v[2], bb1v[3], Bb + 16 * ROWB + kk * 32);
#pragma unroll
            for (int mf = 0; mf < 4; mf++) {
                uint32_t a[4];
                LDSM4(a[0], a[1], a[2], a[3], Ab + mf * (16 * ROWB) + kk * 32);
                MMA4(c[mf][0], a, bb0[0], bb0[2]);
                MMA4(c[mf][1], a, bb0[1], bb0[3]);
                MMA4(c[mf][2], a, bb1v[0], bb1v[2]);
                MMA4(c[mf][3], a, bb1v[1], bb1v[3]);
            }
        }
    }

    // epilogue: scale by routing weight, store fp32
#pragma unroll
    for (int mf = 0; mf < 4; mf++) {
        const int rb = row0 + wm * 64 + mf * 16 + (lane >> 2);
        const float w0 = (rb < cnt)     ? g_sel_w[e * CAP + rb]     : 0.f;
        const float w1 = (rb + 8 < cnt) ? g_sel_w[e * CAP + rb + 8] : 0.f;
#pragma unroll
        for (int nf = 0; nf < 4; nf++) {
            const int col = n0 + wn * 32 + nf * 8 + (lane & 3) * 2;
            if (rb < cnt) {
                float2 o = {c[mf][nf][0] * w0, c[mf][nf][1] * w0};
                *(float2*)(g_y + ((size_t)(e * CAP) + rb) * DIM + col) = o;
            }
            if (rb + 8 < cnt) {
                float2 o = {c[mf][nf][2] * w1, c[mf][nf][3] * w1};
                *(float2*)(g_y + ((size_t)(e * CAP) + rb + 8) * DIM + col) = o;
            }
        }
    }
}

// ---------------- 6) Combine ----------------
__global__ void combine_kernel(float* __restrict__ out) {
    const int t = blockIdx.x;
    const int d = blockIdx.y * 256 + threadIdx.x;
    const int s0 = g_slot_of[t * 2 + 0];
    const int s1 = g_slot_of[t * 2 + 1];
    out[(size_t)t * DIM + d] = g_y[(size_t)s0 * DIM + d] + g_y[(size_t)s1 * DIM + d];
}

// ---------------- launch ----------------
extern "C" void kernel_launch(void* const* d_in, const int* in_sizes, int n_in,
                              void* d_out, int out_size) {
    const float* x      = (const float*)d_in[0];
    const float* w_gate = (const float*)d_in[1];
    const float* w1     = (const float*)d_in[2];
    const float* w3     = (const float*)d_in[3];
    const float* w2     = (const float*)d_in[4];
    float* out = (float*)d_out;
    (void)in_sizes; (void)n_in; (void)out_size;

    cudaFuncSetAttribute(mma1_kernel, cudaFuncAttributeMaxDynamicSharedMemorySize, 4 * STG1);
    cudaFuncSetAttribute(mma2_kernel, cudaFuncAttributeMaxDynamicSharedMemorySize, 4 * STG2);

    __half *xh, *w1h, *w3h, *w2h;
    cudaGetSymbolAddress((void**)&xh,  g_xh);
    cudaGetSymbolAddress((void**)&w1h, g_w1h);
    cudaGetSymbolAddress((void**)&w3h, g_w3h);
    cudaGetSymbolAddress((void**)&w2h, g_w2h);

    router_kernel<<<T_TOK, 256>>>(x, w_gate);
    sort_kernel<<<1, 256>>>();
    cvt_half_kernel<<<2048, 256>>>(x,  xh,  (long)T_TOK * DIM / 4);
    cvt_half_kernel<<<4096, 256>>>(w1, w1h, (long)NE * NI * DIM / 4);
    cvt_half_kernel<<<4096, 256>>>(w3, w3h, (long)NE * NI * DIM / 4);
    cvt_half_kernel<<<4096, 256>>>(w2, w2h, (long)NE * DIM * NI / 4);
    mma1_kernel<<<dim3(NI / 64, NE * (CAP / 128)), 256, 4 * STG1>>>();
    mma2_kernel<<<dim3(DIM / 128, NE * (CAP / 128)), 256, 4 * STG2>>>();
    combine_kernel<<<dim3(T_TOK, DIM / 256), 256>>>(out);
}